// round 1
// baseline (speedup 1.0000x reference)
#include <cuda_runtime.h>
#include <cstdint>

#define CH   256
#define HH   96
#define WW   96
#define BB   4
#define PP   (HH*WW)        // 9216
#define GG   9
#define NGB  (GG*BB)        // 36

typedef unsigned long long ull;

// Scratch: Z[gb][c][p]  (gb = g*4+b), ~340 MB, and inverse norms.
__device__ float g_Z[(size_t)NGB * CH * PP];
__device__ float g_inv[NGB * PP];

__constant__ int c_dy[8] = {-1, -1, -1, 0, 1, 1, 1, 0};
__constant__ int c_dx[8] = {-1,  0,  1, 1, 1, 0, -1, -1};

union F2U { ull u; float2 f; };

__device__ __forceinline__ void ffma2(ull& c, ull a, ull b) {
    asm("fma.rn.f32x2 %0, %1, %2, %0;" : "+l"(c) : "l"(a), "l"(b));
}
__device__ __forceinline__ ull pack2(float x) {
    ull r; asm("mov.b64 %0, {%1, %1};" : "=l"(r) : "f"(x)); return r;
}

// ---------------------------------------------------------------------------
// GEMM: Z[gb] = W3[g] (256x256) @ cen[b] (256x9216)
// Tile 128x128x8, 256 threads, 8x8 micro-tile with packed f32x2 FMA.
// grid: (72, 2, 36)
// ---------------------------------------------------------------------------
__global__ __launch_bounds__(256, 2)
void gemm_kernel(const float* __restrict__ cen, const float* __restrict__ W3) {
    __shared__ float As[8][132];   // padded: conflict-free scattered stores
    __shared__ float Bs[8][128];

    const int t   = threadIdx.x;
    const int gb  = blockIdx.z;
    const float* A  = W3 + (size_t)(gb >> 2) * CH * CH;
    const float* Bg = cen + (size_t)(gb & 3) * CH * PP + blockIdx.x * 128;
    const int row0 = blockIdx.y * 128;

    const int tx = t & 15, ty = t >> 4;
    const int ai = t >> 1, ah = (t & 1) * 4;
    const int bj = t >> 5, bq = (t & 31) * 4;

    ull acc[8][4];
#pragma unroll
    for (int i = 0; i < 8; i++)
#pragma unroll
        for (int j = 0; j < 4; j++) acc[i][j] = 0ull;

    for (int k0 = 0; k0 < CH; k0 += 8) {
        float4 av = *(const float4*)(A + (size_t)(row0 + ai) * CH + k0 + ah);
        As[ah + 0][ai] = av.x; As[ah + 1][ai] = av.y;
        As[ah + 2][ai] = av.z; As[ah + 3][ai] = av.w;
        *(float4*)&Bs[bj][bq] = *(const float4*)(Bg + (size_t)(k0 + bj) * PP + bq);
        __syncthreads();

#pragma unroll
        for (int k = 0; k < 8; k++) {
            float a[8];
            *(float4*)(a)     = *(const float4*)&As[k][ty * 8];
            *(float4*)(a + 4) = *(const float4*)&As[k][ty * 8 + 4];
            ull b2[4];
            const ull* bp = (const ull*)&Bs[k][tx * 8];
            b2[0] = bp[0]; b2[1] = bp[1]; b2[2] = bp[2]; b2[3] = bp[3];
#pragma unroll
            for (int i = 0; i < 8; i++) {
                ull a2 = pack2(a[i]);
#pragma unroll
                for (int j = 0; j < 4; j++) ffma2(acc[i][j], a2, b2[j]);
            }
        }
        __syncthreads();
    }

    float* Zp = g_Z + (size_t)gb * CH * PP + blockIdx.x * 128 + tx * 8;
#pragma unroll
    for (int i = 0; i < 8; i++) {
        int row = row0 + ty * 8 + i;
        F2U u0{acc[i][0]}, u1{acc[i][1]}, u2{acc[i][2]}, u3{acc[i][3]};
        float4 v0 = make_float4(u0.f.x, u0.f.y, u1.f.x, u1.f.y);
        float4 v1 = make_float4(u2.f.x, u2.f.y, u3.f.x, u3.f.y);
        *(float4*)(Zp + (size_t)row * PP)     = v0;
        *(float4*)(Zp + (size_t)row * PP + 4) = v1;
    }
}

// ---------------------------------------------------------------------------
// Channel L2 norms -> inverse norms. One thread per pixel, coalesced over p.
// grid: (36, 36), block 256
// ---------------------------------------------------------------------------
__global__ __launch_bounds__(256)
void norm_kernel() {
    const int gb = blockIdx.y;
    const int p  = blockIdx.x * 256 + threadIdx.x;
    const float* z = g_Z + (size_t)gb * CH * PP + p;
    float a0 = 0.f, a1 = 0.f, a2 = 0.f, a3 = 0.f;
#pragma unroll 4
    for (int i = 0; i < CH; i += 4) {
        float v0 = z[(size_t)(i + 0) * PP];
        float v1 = z[(size_t)(i + 1) * PP];
        float v2 = z[(size_t)(i + 2) * PP];
        float v3 = z[(size_t)(i + 3) * PP];
        a0 = fmaf(v0, v0, a0); a1 = fmaf(v1, v1, a1);
        a2 = fmaf(v2, v2, a2); a3 = fmaf(v3, v3, a3);
    }
    float n = sqrtf((a0 + a1) + (a2 + a3));
    g_inv[gb * PP + p] = 1.0f / fmaxf(n, 1e-12f);
}

// ---------------------------------------------------------------------------
// Epilogue: out = cen + inv8*Z8 - sum_{g<8} inv_g(p+d)*Z_g(p+d)  (masked)
// Block = one (b, h) row-chunk of 32 channels; inv loaded once, reused 32x.
// grid: (96, 8, 4), block 96 (w)
// ---------------------------------------------------------------------------
__global__ __launch_bounds__(96)
void epilogue_kernel(const float* __restrict__ cen, float* __restrict__ out) {
    const int w  = threadIdx.x;
    const int h  = blockIdx.x;
    const int cc = blockIdx.y * 32;
    const int b  = blockIdx.z;
    const int p  = h * WW + w;

    size_t off[9];
    float  sc[9];
#pragma unroll
    for (int g = 0; g < 8; g++) {
        int h2 = h + c_dy[g], w2 = w + c_dx[g];
        bool ok = (h2 >= 0) && (h2 < HH) && (w2 >= 0) && (w2 < WW);
        int p2 = ok ? h2 * WW + w2 : 0;
        int gb = g * 4 + b;
        off[g] = (size_t)gb * CH * PP + p2;
        sc[g]  = ok ? -g_inv[gb * PP + p2] : 0.f;
    }
    {
        int gb = 8 * 4 + b;
        off[8] = (size_t)gb * CH * PP + p;
        sc[8]  = g_inv[gb * PP + p];
    }

    const size_t cbase = (size_t)b * CH * PP + p;
#pragma unroll 4
    for (int ci = 0; ci < 32; ci++) {
        int c = cc + ci;
        size_t cp = (size_t)c * PP;
        float s = cen[cbase + cp];
#pragma unroll
        for (int g = 0; g < 9; g++) s += sc[g] * g_Z[off[g] + cp];
        out[cbase + cp] = s;
    }
}

// ---------------------------------------------------------------------------
extern "C" void kernel_launch(void* const* d_in, const int* in_sizes, int n_in,
                              void* d_out, int out_size) {
    const float* cen = (const float*)d_in[0];   // (4,256,96,96)
    // d_in[1] = W1, d_in[2] = W2 : mathematically dead (softmax over size-1 axis == 1)
    const float* W3  = (const float*)d_in[3];   // (9,256,256)
    float* out = (float*)d_out;

    dim3 gg(PP / 128, CH / 128, NGB);           // (72, 2, 36)
    gemm_kernel<<<gg, 256>>>(cen, W3);

    norm_kernel<<<dim3(PP / 256, NGB), 256>>>();

    epilogue_kernel<<<dim3(HH, CH / 32, BB), WW>>>(cen, out);
}

// round 3
// speedup vs baseline: 1.8871x; 1.8871x over previous
#include <cuda_runtime.h>
#include <cstdint>

#define CH   256
#define HH   96
#define WW   96
#define BB   4
#define PP   (HH*WW)        // 9216
#define GG   9
#define NGB  (GG*BB)        // 36

__device__ float g_Z[(size_t)NGB * CH * PP];   // Z[gb][c][p]
__device__ float g_ssq[NGB * PP];              // per-pixel sum of squares

__constant__ int c_dy[8] = {-1, -1, -1, 0, 1, 1, 1, 0};
__constant__ int c_dx[8] = {-1,  0,  1, 1, 1, 0, -1, -1};

// smem float-index layout (fragment-permuted tiles)
//   As[stage][k8][m16] tile of 132 floats (128 used + pad)
//   Bs[stage][k8][n8]  tile of 66 floats  (64 used + pad)
#define ASZ (2*4*8*132)          // 8448 floats
#define BSZ (2*4*16*66)          // 8448 floats
#define SMEM_BYTES ((ASZ + BSZ) * 4)   // 67584

__device__ __forceinline__ int As_idx(int s, int k8, int m16) {
    return ((s * 4 + k8) * 8 + m16) * 132;
}
__device__ __forceinline__ int Bs_idx(int s, int k8, int n8) {
    return ASZ + ((s * 4 + k8) * 16 + n8) * 66;
}
__device__ __forceinline__ uint32_t to_tf32(float f) {
    uint32_t u;
    asm("cvt.rna.tf32.f32 %0, %1;" : "=r"(u) : "f"(f));
    return u;
}
__device__ __forceinline__ void mma8(float* d, const uint32_t* a, const uint32_t* b) {
    asm volatile(
        "mma.sync.aligned.m16n8k8.row.col.f32.tf32.tf32.f32 "
        "{%0,%1,%2,%3},{%4,%5,%6,%7},{%8,%9},{%0,%1,%2,%3};"
        : "+f"(d[0]), "+f"(d[1]), "+f"(d[2]), "+f"(d[3])
        : "r"(a[0]), "r"(a[1]), "r"(a[2]), "r"(a[3]), "r"(b[0]), "r"(b[1]));
}

// ---------------------------------------------------------------------------
// zero g_ssq (graph-replayed every launch)
// ---------------------------------------------------------------------------
__global__ __launch_bounds__(256)
void zero_ssq_kernel() {
    int i = blockIdx.x * 256 + threadIdx.x;
    if (i < NGB * PP) g_ssq[i] = 0.f;
}

// ---------------------------------------------------------------------------
// tf32 mma.sync GEMM: Z[gb](128 rows) = W3[g][rows] @ cen[b], + fused sumsq.
// grid (72 px-tiles, 2 m-halves, 36 gb), 256 threads.
// ---------------------------------------------------------------------------
__global__ __launch_bounds__(256, 1)
void gemm_kernel(const float* __restrict__ cen, const float* __restrict__ W3) {
    extern __shared__ float sm[];
    const int t = threadIdx.x;
    const int lane = t & 31, wid = t >> 5;
    const int mwarp = wid >> 2, nwarp = wid & 3;
    const int grp = lane >> 2, tig = lane & 3;

    const int gb = blockIdx.z;
    const int g = gb >> 2, b = gb & 3;
    const int p0 = blockIdx.x * 128;
    const int r0 = blockIdx.y * 128;

    const float* Ag = W3 + (size_t)g * CH * CH + (size_t)r0 * CH;
    const float* Bg = cen + (size_t)b * CH * PP + p0;

    float acc[4][4][4];
#pragma unroll
    for (int i = 0; i < 4; i++)
#pragma unroll
        for (int j = 0; j < 4; j++)
#pragma unroll
            for (int q = 0; q < 4; q++) acc[i][j][q] = 0.f;

    float4 Av[4], Bv[4];

    // prologue: load + store chunk 0
#pragma unroll
    for (int q = 0; q < 4; q++) {
        int idx = q * 256 + t;
        Av[q] = *(const float4*)(Ag + (size_t)(idx >> 3) * CH + (idx & 7) * 4);
        Bv[q] = *(const float4*)(Bg + (size_t)(q * 8 + (t >> 5)) * PP + (t & 31) * 4);
    }
#pragma unroll
    for (int q = 0; q < 4; q++) {
        int idx = q * 256 + t;
        int m = idx >> 3, kf = idx & 7;
        const float* av = (const float*)&Av[q];
        const float* bv = (const float*)&Bv[q];
        int kB = q * 8 + (t >> 5), n4 = (t & 31) * 4;
#pragma unroll
        for (int jj = 0; jj < 4; jj++) {
            int kk = kf * 4 + jj;
            int la = (m & 7) * 4 + (kk & 3) + ((m >> 3) & 1) * 0; // grp*4+tig (m&15 split below)
            // A scatter
            {
                int m16 = m >> 4, mr = m & 15, gA = mr & 7, hA = mr >> 3;
                sm[As_idx(0, kk >> 3, m16) + (gA * 4 + (kk & 3)) * 4 + hA + 2 * ((kk & 7) >> 2)]
                    = __uint_as_float(to_tf32(av[jj]));
            }
            // B scatter
            {
                int n = n4 + jj, n8 = n >> 3, nr = n & 7, kr = kB & 7;
                sm[Bs_idx(0, kB >> 3, n8) + (nr * 4 + (kr & 3)) * 2 + (kr >> 2)]
                    = __uint_as_float(to_tf32(bv[jj]));
            }
            (void)la;
        }
    }
    __syncthreads();

    for (int c = 0; c < 8; c++) {
        const int s = c & 1;
        // load next chunk to regs
        if (c < 7) {
            int k0 = (c + 1) * 32;
#pragma unroll
            for (int q = 0; q < 4; q++) {
                int idx = q * 256 + t;
                Av[q] = *(const float4*)(Ag + (size_t)(idx >> 3) * CH + k0 + (idx & 7) * 4);
                Bv[q] = *(const float4*)(Bg + (size_t)(k0 + q * 8 + (t >> 5)) * PP + (t & 31) * 4);
            }
        }
        // compute current
#pragma unroll
        for (int k8 = 0; k8 < 4; k8++) {
            uint32_t af[4][4], bf[4][2];
#pragma unroll
            for (int i = 0; i < 4; i++)
                *(uint4*)af[i] = *(const uint4*)&sm[As_idx(s, k8, mwarp * 4 + i) + lane * 4];
#pragma unroll
            for (int j = 0; j < 4; j++)
                *(uint2*)bf[j] = *(const uint2*)&sm[Bs_idx(s, k8, nwarp * 4 + j) + lane * 2];
#pragma unroll
            for (int i = 0; i < 4; i++)
#pragma unroll
                for (int j = 0; j < 4; j++) mma8(acc[i][j], af[i], bf[j]);
        }
        if (c < 7) {
            __syncthreads();
            int s2 = s ^ 1;
#pragma unroll
            for (int q = 0; q < 4; q++) {
                int idx = q * 256 + t;
                int m = idx >> 3, kf = idx & 7;
                const float* av = (const float*)&Av[q];
                const float* bv = (const float*)&Bv[q];
                int kB = q * 8 + (t >> 5), n4 = (t & 31) * 4;
#pragma unroll
                for (int jj = 0; jj < 4; jj++) {
                    int kk = kf * 4 + jj;
                    int m16 = m >> 4, mr = m & 15, gA = mr & 7, hA = mr >> 3;
                    sm[As_idx(s2, kk >> 3, m16) + (gA * 4 + (kk & 3)) * 4 + hA + 2 * ((kk & 7) >> 2)]
                        = __uint_as_float(to_tf32(av[jj]));
                    int n = n4 + jj, n8 = n >> 3, nr = n & 7, kr = kB & 7;
                    sm[Bs_idx(s2, kB >> 3, n8) + (nr * 4 + (kr & 3)) * 2 + (kr >> 2)]
                        = __uint_as_float(to_tf32(bv[jj]));
                }
            }
            __syncthreads();
        }
    }

    // Store Z + fused per-pixel sumsq.
    float* Zb = g_Z + ((size_t)gb * CH + r0 + mwarp * 64) * PP + p0 + nwarp * 32;
#pragma unroll
    for (int j = 0; j < 4; j++) {
        float s0 = 0.f, s1 = 0.f;
#pragma unroll
        for (int i = 0; i < 4; i++) {
            float* d = acc[i][j];
            s0 = fmaf(d[0], d[0], fmaf(d[2], d[2], s0));
            s1 = fmaf(d[1], d[1], fmaf(d[3], d[3], s1));
            int row = i * 16 + grp;
            int col = j * 8 + tig * 2;
            *(float2*)(Zb + (size_t)row * PP + col)       = make_float2(d[0], d[1]);
            *(float2*)(Zb + (size_t)(row + 8) * PP + col) = make_float2(d[2], d[3]);
        }
#pragma unroll
        for (int off = 4; off < 32; off <<= 1) {
            s0 += __shfl_xor_sync(0xffffffffu, s0, off);
            s1 += __shfl_xor_sync(0xffffffffu, s1, off);
        }
        if (grp == 0) {
            int col = p0 + nwarp * 32 + j * 8 + tig * 2;
            atomicAdd(&g_ssq[gb * PP + col],     s0);
            atomicAdd(&g_ssq[gb * PP + col + 1], s1);
        }
    }
}

// ---------------------------------------------------------------------------
// Epilogue: out = cen + inv8*Z8 - sum_{g<8} inv_g(p+d)*Z_g(p+d)
// inv computed inline from g_ssq.
// ---------------------------------------------------------------------------
__global__ __launch_bounds__(96)
void epilogue_kernel(const float* __restrict__ cen, float* __restrict__ out) {
    const int w  = threadIdx.x;
    const int h  = blockIdx.x;
    const int cc = blockIdx.y * 32;
    const int b  = blockIdx.z;
    const int p  = h * WW + w;

    size_t off[9];
    float  sc[9];
#pragma unroll
    for (int g = 0; g < 8; g++) {
        int h2 = h + c_dy[g], w2 = w + c_dx[g];
        bool ok = (h2 >= 0) && (h2 < HH) && (w2 >= 0) && (w2 < WW);
        int p2 = ok ? h2 * WW + w2 : 0;
        int gb = g * 4 + b;
        off[g] = (size_t)gb * CH * PP + p2;
        float n = sqrtf(g_ssq[gb * PP + p2]);
        sc[g]  = ok ? -1.0f / fmaxf(n, 1e-12f) : 0.f;
    }
    {
        int gb = 8 * 4 + b;
        off[8] = (size_t)gb * CH * PP + p;
        float n = sqrtf(g_ssq[gb * PP + p]);
        sc[8]  = 1.0f / fmaxf(n, 1e-12f);
    }

    const size_t cbase = (size_t)b * CH * PP + p;
#pragma unroll 4
    for (int ci = 0; ci < 32; ci++) {
        size_t cp = (size_t)(cc + ci) * PP;
        float s = cen[cbase + cp];
#pragma unroll
        for (int g = 0; g < 9; g++) s += sc[g] * g_Z[off[g] + cp];
        out[cbase + cp] = s;
    }
}

// ---------------------------------------------------------------------------
extern "C" void kernel_launch(void* const* d_in, const int* in_sizes, int n_in,
                              void* d_out, int out_size) {
    const float* cen = (const float*)d_in[0];   // (4,256,96,96)
    // d_in[1]=W1, d_in[2]=W2 dead (softmax over size-1 axis == 1)
    const float* W3  = (const float*)d_in[3];   // (9,256,256)
    float* out = (float*)d_out;

    cudaFuncSetAttribute(gemm_kernel, cudaFuncAttributeMaxDynamicSharedMemorySize, SMEM_BYTES);

    zero_ssq_kernel<<<(NGB * PP + 255) / 256, 256>>>();
    gemm_kernel<<<dim3(PP / 128, 2, NGB), 256, SMEM_BYTES>>>(cen, W3);
    epilogue_kernel<<<dim3(HH, CH / 32, BB), WW>>>(cen, out);
}

// round 7
// speedup vs baseline: 2.9863x; 1.5825x over previous
#include <cuda_runtime.h>
#include <cuda_fp16.h>
#include <cstdint>

#define CH   256
#define HH   96
#define WW   96
#define BB   4
#define PP   (HH*WW)        // 9216
#define GG   9
#define NGB  (GG*BB)        // 36

#define AST 36              // A smem row stride (floats)
#define BST 136             // B smem row stride (floats)
#define STAGE_F 8960        // floats per stage: A 128*36=4608, B 32*136=4352
#define B_OFF_F 4608
#define SSQ_OFF_F (2*STAGE_F)
#define SMEM_BYTES ((2*STAGE_F + 128) * 4)   // 72192

__device__ __half g_Zh[(size_t)NGB * CH * PP];   // Z[gb][c][p] fp16
__device__ float  g_ssq2[2][NGB * PP];           // per-m-half partial sumsq

__constant__ int c_dy[8] = {-1, -1, -1, 0, 1, 1, 1, 0};
__constant__ int c_dx[8] = {-1,  0,  1, 1, 1, 0, -1, -1};

__device__ __forceinline__ uint32_t smem_u32(const void* p) {
    uint32_t a;
    asm("{ .reg .u64 t; cvta.to.shared.u64 t, %1; cvt.u32.u64 %0, t; }" : "=r"(a) : "l"(p));
    return a;
}
#define CPA16(dst, src) asm volatile("cp.async.cg.shared.global [%0], [%1], 16;" :: "r"(dst), "l"(src) : "memory")
#define CPA_COMMIT()    asm volatile("cp.async.commit_group;" ::: "memory")
#define CPA_WAIT1()     asm volatile("cp.async.wait_group 1;" ::: "memory")
#define CPA_WAIT0()     asm volatile("cp.async.wait_group 0;" ::: "memory")

__device__ __forceinline__ void mma8(float* d, const uint32_t* a, const uint32_t* b) {
    asm volatile(
        "mma.sync.aligned.m16n8k8.row.col.f32.tf32.tf32.f32 "
        "{%0,%1,%2,%3},{%4,%5,%6,%7},{%8,%9},{%0,%1,%2,%3};"
        : "+f"(d[0]), "+f"(d[1]), "+f"(d[2]), "+f"(d[3])
        : "r"(a[0]), "r"(a[1]), "r"(a[2]), "r"(a[3]), "r"(b[0]), "r"(b[1]));
}

// ---------------------------------------------------------------------------
// tf32 mma.sync GEMM, plain smem layouts + cp.async double buffer.
// Z[gb] rows [r0,r0+128) = W3[g][rows] @ cen[b][:, p0:p0+128], fp16 out,
// fused per-pixel partial sumsq. grid (72, 2, 36), 256 threads.
// ---------------------------------------------------------------------------
__global__ __launch_bounds__(256, 2)
void gemm_kernel(const float* __restrict__ cen, const float* __restrict__ W3) {
    extern __shared__ float sm[];
    const uint32_t sb = smem_u32(sm);
    const int t = threadIdx.x;
    const int lane = t & 31, wid = t >> 5;
    const int mwarp = wid >> 2, nwarp = wid & 3;
    const int grp = lane >> 2, tig = lane & 3;

    const int gb = blockIdx.z;
    const int g = gb >> 2, b = gb & 3;
    const int p0 = blockIdx.x * 128;
    const int r0 = blockIdx.y * 128;

    const float* Ag = W3 + (size_t)g * CH * CH + (size_t)r0 * CH;
    const float* Bg = cen + (size_t)b * CH * PP + p0;

    if (t < 128) sm[SSQ_OFF_F + t] = 0.f;

#define ISSUE_CHUNK(c, s) do {                                                  \
    const int k0 = (c) * 32;                                                    \
    _Pragma("unroll")                                                           \
    for (int q = 0; q < 4; q++) {                                               \
        int u = q * 256 + t;                                                    \
        int m = u >> 3, k4 = u & 7;                                             \
        uint32_t dst = sb + ((s) * STAGE_F + m * AST) * 4 + k4 * 16;            \
        CPA16(dst, Ag + (size_t)m * CH + k0 + k4 * 4);                          \
    }                                                                           \
    _Pragma("unroll")                                                           \
    for (int q = 0; q < 4; q++) {                                               \
        int u = q * 256 + t;                                                    \
        int kr = u >> 5, c16 = u & 31;                                          \
        uint32_t dst = sb + ((s) * STAGE_F + B_OFF_F + kr * BST) * 4 + c16 * 16;\
        CPA16(dst, Bg + (size_t)(k0 + kr) * PP + c16 * 4);                      \
    }                                                                           \
    CPA_COMMIT();                                                               \
} while (0)

    ISSUE_CHUNK(0, 0);
    ISSUE_CHUNK(1, 1);

    float acc[4][4][4];
#pragma unroll
    for (int i = 0; i < 4; i++)
#pragma unroll
        for (int j = 0; j < 4; j++)
#pragma unroll
            for (int q = 0; q < 4; q++) acc[i][j][q] = 0.f;

    for (int c = 0; c < 8; c++) {
        const int s = c & 1;
        if (c < 7) CPA_WAIT1(); else CPA_WAIT0();
        __syncthreads();

        const uint32_t* Sa = (const uint32_t*)(sm + s * STAGE_F);
        const uint32_t* Sb = (const uint32_t*)(sm + s * STAGE_F + B_OFF_F);
#pragma unroll
        for (int k8 = 0; k8 < 4; k8++) {
            uint32_t af[4][4], bf[4][2];
            const int kk = k8 * 8;
#pragma unroll
            for (int i = 0; i < 4; i++) {
                int mrow = mwarp * 64 + i * 16 + grp;
                af[i][0] = Sa[(size_t)mrow * AST + kk + tig];
                af[i][1] = Sa[(size_t)(mrow + 8) * AST + kk + tig];
                af[i][2] = Sa[(size_t)mrow * AST + kk + tig + 4];
                af[i][3] = Sa[(size_t)(mrow + 8) * AST + kk + tig + 4];
            }
#pragma unroll
            for (int j = 0; j < 4; j++) {
                int ncol = nwarp * 32 + j * 8 + grp;
                bf[j][0] = Sb[(size_t)(kk + tig) * BST + ncol];
                bf[j][1] = Sb[(size_t)(kk + tig + 4) * BST + ncol];
            }
#pragma unroll
            for (int i = 0; i < 4; i++)
#pragma unroll
                for (int j = 0; j < 4; j++) mma8(acc[i][j], af[i], bf[j]);
        }
        if (c < 6) {
            __syncthreads();
            ISSUE_CHUNK(c + 2, s);
        }
    }

    // Store Z (fp16) + fused per-pixel sumsq.
    __half* Zb = g_Zh + ((size_t)gb * CH + r0 + mwarp * 64) * PP + p0 + nwarp * 32;
    float* ssq = sm + SSQ_OFF_F;
#pragma unroll
    for (int j = 0; j < 4; j++) {
        float s0 = 0.f, s1 = 0.f;
#pragma unroll
        for (int i = 0; i < 4; i++) {
            float* d = acc[i][j];
            s0 = fmaf(d[0], d[0], fmaf(d[2], d[2], s0));
            s1 = fmaf(d[1], d[1], fmaf(d[3], d[3], s1));
            int row = i * 16 + grp;
            int col = j * 8 + tig * 2;
            *(__half2*)(Zb + (size_t)row * PP + col)       = __floats2half2_rn(d[0], d[1]);
            *(__half2*)(Zb + (size_t)(row + 8) * PP + col) = __floats2half2_rn(d[2], d[3]);
        }
#pragma unroll
        for (int off = 4; off < 32; off <<= 1) {
            s0 += __shfl_xor_sync(0xffffffffu, s0, off);
            s1 += __shfl_xor_sync(0xffffffffu, s1, off);
        }
        if (grp == 0) {
            atomicAdd(&ssq[nwarp * 32 + j * 8 + tig * 2],     s0);
            atomicAdd(&ssq[nwarp * 32 + j * 8 + tig * 2 + 1], s1);
        }
    }
    __syncthreads();
    if (t < 128)
        g_ssq2[blockIdx.y][gb * PP + p0 + t] = ssq[t];
}

// ---------------------------------------------------------------------------
// Epilogue: out = cen + inv8*Z8 - sum_{g<8} inv_g(p+d)*Z_g(p+d)
// inv from the two partial sumsq halves. grid (48, 8, 4), 192 threads.
// ---------------------------------------------------------------------------
__global__ __launch_bounds__(192)
void epilogue_kernel(const float* __restrict__ cen, float* __restrict__ out) {
    const int w  = threadIdx.x % 96;
    const int h  = blockIdx.x * 2 + threadIdx.x / 96;
    const int cc = blockIdx.y * 32;
    const int b  = blockIdx.z;
    const int p  = h * WW + w;

    size_t off[9];
    float  sc[9];
#pragma unroll
    for (int g = 0; g < 8; g++) {
        int h2 = h + c_dy[g], w2 = w + c_dx[g];
        bool ok = (h2 >= 0) && (h2 < HH) && (w2 >= 0) && (w2 < WW);
        int p2 = ok ? h2 * WW + w2 : 0;
        int gb = g * 4 + b;
        off[g] = (size_t)gb * CH * PP + p2;
        float n = sqrtf(g_ssq2[0][gb * PP + p2] + g_ssq2[1][gb * PP + p2]);
        sc[g]  = ok ? -1.0f / fmaxf(n, 1e-12f) : 0.f;
    }
    {
        int gb = 8 * 4 + b;
        off[8] = (size_t)gb * CH * PP + p;
        float n = sqrtf(g_ssq2[0][gb * PP + p] + g_ssq2[1][gb * PP + p]);
        sc[8]  = 1.0f / fmaxf(n, 1e-12f);
    }

    const size_t cbase = (size_t)b * CH * PP + p;
#pragma unroll 4
    for (int ci = 0; ci < 32; ci++) {
        size_t cp = (size_t)(cc + ci) * PP;
        float s = cen[cbase + cp];
#pragma unroll
        for (int g = 0; g < 9; g++)
            s += sc[g] * __half2float(g_Zh[off[g] + cp]);
        out[cbase + cp] = s;
    }
}

// ---------------------------------------------------------------------------
extern "C" void kernel_launch(void* const* d_in, const int* in_sizes, int n_in,
                              void* d_out, int out_size) {
    const float* cen = (const float*)d_in[0];   // (4,256,96,96)
    // d_in[1]=W1, d_in[2]=W2 dead (softmax over size-1 axis == 1)
    const float* W3  = (const float*)d_in[3];   // (9,256,256)
    float* out = (float*)d_out;

    cudaFuncSetAttribute(gemm_kernel, cudaFuncAttributeMaxDynamicSharedMemorySize, SMEM_BYTES);

    gemm_kernel<<<dim3(PP / 128, 2, NGB), 256, SMEM_BYTES>>>(cen, W3);
    epilogue_kernel<<<dim3(HH / 2, CH / 32, BB), 192>>>(cen, out);
}

// round 8
// speedup vs baseline: 3.9773x; 1.3319x over previous
#include <cuda_runtime.h>
#include <cuda_fp16.h>
#include <cuda_bf16.h>
#include <cstdint>

#define CH   256
#define HH   96
#define WW   96
#define BB   4
#define PP   (HH*WW)        // 9216
#define GG   9
#define NGB  (GG*BB)        // 36

// bf16 smem tiles: A 128 rows x 40 halves (80B stride), B 32 rows x 136 halves (272B)
#define ASTRIDE_B 80
#define BSTRIDE_B 272
#define B_OFF     10240u                 // A stage bytes = 128*80
#define STAGE     18944u                 // + B 32*272 = 8704
#define SSQ_OFF   (2*STAGE)              // 37888
#define SMEM_BYTES (SSQ_OFF + 512)       // 38400

__device__ __nv_bfloat16 g_cenh[(size_t)BB * CH * PP];
__device__ __nv_bfloat16 g_w3h[(size_t)GG * CH * CH];
__device__ __half g_Zh[(size_t)NGB * CH * PP];   // Z[gb][c][p] fp16
__device__ float  g_ssq2[2][NGB * PP];           // per-m-half partial sumsq

__constant__ int c_dy[8] = {-1, -1, -1, 0, 1, 1, 1, 0};
__constant__ int c_dx[8] = {-1,  0,  1, 1, 1, 0, -1, -1};

__device__ __forceinline__ uint32_t smem_u32(const void* p) {
    uint32_t a;
    asm("{ .reg .u64 t; cvta.to.shared.u64 t, %1; cvt.u32.u64 %0, t; }" : "=r"(a) : "l"(p));
    return a;
}
#define CPA16(dst, src) asm volatile("cp.async.cg.shared.global [%0], [%1], 16;" :: "r"(dst), "l"(src) : "memory")
#define CPA_COMMIT()    asm volatile("cp.async.commit_group;" ::: "memory")
#define CPA_WAIT1()     asm volatile("cp.async.wait_group 1;" ::: "memory")
#define CPA_WAIT0()     asm volatile("cp.async.wait_group 0;" ::: "memory")

#define LDSM_X4(r, a) \
    asm volatile("ldmatrix.sync.aligned.m8n8.x4.shared.b16 {%0,%1,%2,%3}, [%4];" \
        : "=r"((r)[0]), "=r"((r)[1]), "=r"((r)[2]), "=r"((r)[3]) : "r"(a))
#define LDSM_X4T(r, a) \
    asm volatile("ldmatrix.sync.aligned.m8n8.x4.trans.shared.b16 {%0,%1,%2,%3}, [%4];" \
        : "=r"((r)[0]), "=r"((r)[1]), "=r"((r)[2]), "=r"((r)[3]) : "r"(a))

__device__ __forceinline__ void mma16(float* d, const uint32_t* a, const uint32_t* b) {
    asm volatile(
        "mma.sync.aligned.m16n8k16.row.col.f32.bf16.bf16.f32 "
        "{%0,%1,%2,%3},{%4,%5,%6,%7},{%8,%9},{%0,%1,%2,%3};"
        : "+f"(d[0]), "+f"(d[1]), "+f"(d[2]), "+f"(d[3])
        : "r"(a[0]), "r"(a[1]), "r"(a[2]), "r"(a[3]), "r"(b[0]), "r"(b[1]));
}

// ---------------------------------------------------------------------------
// fp32 -> bf16 convert for cen and W3 (one float4 -> 4 bf16 per thread).
// ---------------------------------------------------------------------------
#define N_CEN4 (BB*CH*PP/4)   // 2359296
#define N_W34  (GG*CH*CH/4)   // 147456
__global__ __launch_bounds__(512)
void convert_kernel(const float* __restrict__ cen, const float* __restrict__ W3) {
    int i = blockIdx.x * 512 + threadIdx.x;
    float4 v;
    __nv_bfloat162* dst;
    if (i < N_CEN4) {
        v = ((const float4*)cen)[i];
        dst = (__nv_bfloat162*)g_cenh + i * 2;
    } else {
        int j = i - N_CEN4;
        if (j >= N_W34) return;
        v = ((const float4*)W3)[j];
        dst = (__nv_bfloat162*)g_w3h + j * 2;
    }
    dst[0] = __floats2bfloat162_rn(v.x, v.y);
    dst[1] = __floats2bfloat162_rn(v.z, v.w);
}

// ---------------------------------------------------------------------------
// bf16 mma.sync GEMM (m16n8k16, ldmatrix) + cp.async double buffer.
// Z[gb] rows [r0,r0+128) = W3[g] @ cen[b][:, p0:p0+128], fp16 out,
// fused per-pixel partial sumsq. grid (72, 2, 36), 256 threads.
// ---------------------------------------------------------------------------
__global__ __launch_bounds__(256, 2)
void gemm_kernel() {
    extern __shared__ float sm[];
    const uint32_t sb = smem_u32(sm);
    const int t = threadIdx.x;
    const int lane = t & 31, wid = t >> 5;
    const int mwarp = wid >> 2, nwarp = wid & 3;
    const int grp = lane >> 2, tig = lane & 3;

    const int gb = blockIdx.z;
    const int g = gb >> 2, b = gb & 3;
    const int p0 = blockIdx.x * 128;
    const int r0 = blockIdx.y * 128;

    const __nv_bfloat16* Ag = g_w3h + (size_t)g * CH * CH + (size_t)r0 * CH;
    const __nv_bfloat16* Bg = g_cenh + (size_t)b * CH * PP + p0;

    if (t < 128) sm[SSQ_OFF / 4 + t] = 0.f;

#define ISSUE_CHUNK(c, s) do {                                                  \
    const int k0 = (c) * 32;                                                    \
    _Pragma("unroll")                                                           \
    for (int q = 0; q < 2; q++) {                                               \
        int u = q * 256 + t;                                                    \
        int m = u >> 2, k4 = u & 3;                                             \
        uint32_t dst = sb + (s) * STAGE + m * ASTRIDE_B + k4 * 16;              \
        CPA16(dst, Ag + (size_t)m * CH + k0 + k4 * 8);                          \
    }                                                                           \
    _Pragma("unroll")                                                           \
    for (int q = 0; q < 2; q++) {                                               \
        int u = q * 256 + t;                                                    \
        int kr = u >> 4, c8 = u & 15;                                           \
        uint32_t dst = sb + (s) * STAGE + B_OFF + kr * BSTRIDE_B + c8 * 16;     \
        CPA16(dst, Bg + (size_t)(k0 + kr) * PP + c8 * 8);                       \
    }                                                                           \
    CPA_COMMIT();                                                               \
} while (0)

    ISSUE_CHUNK(0, 0);
    ISSUE_CHUNK(1, 1);

    float acc[4][4][4];
#pragma unroll
    for (int i = 0; i < 4; i++)
#pragma unroll
        for (int j = 0; j < 4; j++)
#pragma unroll
            for (int q = 0; q < 4; q++) acc[i][j][q] = 0.f;

    const int arow = lane & 15, ahl = lane >> 4;   // ldmatrix lane roles

    for (int c = 0; c < 8; c++) {
        const int s = c & 1;
        if (c < 7) CPA_WAIT1(); else CPA_WAIT0();
        __syncthreads();

        const uint32_t sA = sb + s * STAGE;
        const uint32_t sB = sA + B_OFF;
#pragma unroll
        for (int k16 = 0; k16 < 2; k16++) {
            uint32_t af[4][4], bf[4][2];
#pragma unroll
            for (int i = 0; i < 4; i++) {
                uint32_t a = sA + (mwarp * 64 + i * 16 + arow) * ASTRIDE_B
                           + (ahl * 8 + k16 * 16) * 2;
                LDSM_X4(af[i], a);
            }
#pragma unroll
            for (int jp = 0; jp < 2; jp++) {
                uint32_t r[4];
                uint32_t a = sB + (k16 * 16 + arow) * BSTRIDE_B
                           + (nwarp * 32 + jp * 16 + ahl * 8) * 2;
                LDSM_X4T(r, a);
                bf[jp * 2][0] = r[0]; bf[jp * 2][1] = r[1];
                bf[jp * 2 + 1][0] = r[2]; bf[jp * 2 + 1][1] = r[3];
            }
#pragma unroll
            for (int i = 0; i < 4; i++)
#pragma unroll
                for (int j = 0; j < 4; j++) mma16(acc[i][j], af[i], bf[j]);
        }
        if (c < 6) {
            __syncthreads();
            ISSUE_CHUNK(c + 2, s);
        }
    }

    // Store Z (fp16) + fused per-pixel sumsq.
    __half* Zb = g_Zh + ((size_t)gb * CH + r0 + mwarp * 64) * PP + p0 + nwarp * 32;
    float* ssq = sm + SSQ_OFF / 4;
#pragma unroll
    for (int j = 0; j < 4; j++) {
        float s0 = 0.f, s1 = 0.f;
#pragma unroll
        for (int i = 0; i < 4; i++) {
            float* d = acc[i][j];
            s0 = fmaf(d[0], d[0], fmaf(d[2], d[2], s0));
            s1 = fmaf(d[1], d[1], fmaf(d[3], d[3], s1));
            int row = i * 16 + grp;
            int col = j * 8 + tig * 2;
            *(__half2*)(Zb + (size_t)row * PP + col)       = __floats2half2_rn(d[0], d[1]);
            *(__half2*)(Zb + (size_t)(row + 8) * PP + col) = __floats2half2_rn(d[2], d[3]);
        }
#pragma unroll
        for (int off = 4; off < 32; off <<= 1) {
            s0 += __shfl_xor_sync(0xffffffffu, s0, off);
            s1 += __shfl_xor_sync(0xffffffffu, s1, off);
        }
        if (grp == 0) {
            atomicAdd(&ssq[nwarp * 32 + j * 8 + tig * 2],     s0);
            atomicAdd(&ssq[nwarp * 32 + j * 8 + tig * 2 + 1], s1);
        }
    }
    __syncthreads();
    if (t < 128)
        g_ssq2[blockIdx.y][gb * PP + p0 + t] = ssq[t];
}

// ---------------------------------------------------------------------------
// Epilogue: out = cen + inv8*Z8 - sum_{g<8} inv_g(p+d)*Z_g(p+d)
// ---------------------------------------------------------------------------
__global__ __launch_bounds__(192)
void epilogue_kernel(const float* __restrict__ cen, float* __restrict__ out) {
    const int w  = threadIdx.x % 96;
    const int h  = blockIdx.x * 2 + threadIdx.x / 96;
    const int cc = blockIdx.y * 32;
    const int b  = blockIdx.z;
    const int p  = h * WW + w;

    size_t off[9];
    float  sc[9];
#pragma unroll
    for (int g = 0; g < 8; g++) {
        int h2 = h + c_dy[g], w2 = w + c_dx[g];
        bool ok = (h2 >= 0) && (h2 < HH) && (w2 >= 0) && (w2 < WW);
        int p2 = ok ? h2 * WW + w2 : 0;
        int gb = g * 4 + b;
        off[g] = (size_t)gb * CH * PP + p2;
        float n = sqrtf(g_ssq2[0][gb * PP + p2] + g_ssq2[1][gb * PP + p2]);
        sc[g]  = ok ? -1.0f / fmaxf(n, 1e-12f) : 0.f;
    }
    {
        int gb = 8 * 4 + b;
        off[8] = (size_t)gb * CH * PP + p;
        float n = sqrtf(g_ssq2[0][gb * PP + p] + g_ssq2[1][gb * PP + p]);
        sc[8]  = 1.0f / fmaxf(n, 1e-12f);
    }

    const size_t cbase = (size_t)b * CH * PP + p;
#pragma unroll 4
    for (int ci = 0; ci < 32; ci++) {
        size_t cp = (size_t)(cc + ci) * PP;
        float s = cen[cbase + cp];
#pragma unroll
        for (int g = 0; g < 9; g++)
            s += sc[g] * __half2float(g_Zh[off[g] + cp]);
        out[cbase + cp] = s;
    }
}

// ---------------------------------------------------------------------------
extern "C" void kernel_launch(void* const* d_in, const int* in_sizes, int n_in,
                              void* d_out, int out_size) {
    const float* cen = (const float*)d_in[0];   // (4,256,96,96)
    // d_in[1]=W1, d_in[2]=W2 dead (softmax over size-1 axis == 1)
    const float* W3  = (const float*)d_in[3];   // (9,256,256)
    float* out = (float*)d_out;

    cudaFuncSetAttribute(gemm_kernel, cudaFuncAttributeMaxDynamicSharedMemorySize, SMEM_BYTES);

    convert_kernel<<<(N_CEN4 + N_W34 + 511) / 512, 512>>>(cen, W3);
    gemm_kernel<<<dim3(PP / 128, 2, NGB), 256, SMEM_BYTES>>>();
    epilogue_kernel<<<dim3(HH / 2, CH / 32, BB), 192>>>(cen, out);
}